// round 5
// baseline (speedup 1.0000x reference)
#include <cuda_runtime.h>
#include <math.h>
#include <stdint.h>

// Problem constants
#define BB 8
#define TT 4096
#define NM 1024
#define HS 128
#define MROWS (BB * TT)
#define NQT128 (TT / 128)        // 32 query tiles of 128 rows

// Scratch
__device__ float g_k [MROWS * HS];   // raw projection (V), tf32-rounded
__device__ float g_kr[MROWS * HS];   // RoPE'd projection (Q,K), tf32-rounded

// ---------------------------------------------------------------------------
__device__ __forceinline__ float fast_exp2(float x) {
    float y;
    asm("ex2.approx.ftz.f32 %0, %1;" : "=f"(y) : "f"(x));
    return y;
}
__device__ __forceinline__ float f2tf(float x) {
    uint32_t r;
    asm("cvt.rna.tf32.f32 %0, %1;" : "=r"(r) : "f"(x));
    return __uint_as_float(r);
}
__device__ __forceinline__ void mma_tf32(float c[4],
                                         uint32_t a0, uint32_t a1, uint32_t a2, uint32_t a3,
                                         uint32_t b0, uint32_t b1) {
    asm volatile(
        "mma.sync.aligned.m16n8k8.row.col.f32.tf32.tf32.f32 "
        "{%0,%1,%2,%3}, {%4,%5,%6,%7}, {%8,%9}, {%0,%1,%2,%3};\n"
        : "+f"(c[0]), "+f"(c[1]), "+f"(c[2]), "+f"(c[3])
        : "r"(a0), "r"(a1), "r"(a2), "r"(a3), "r"(b0), "r"(b1));
}
__device__ __forceinline__ void cpa16(uint32_t saddr, const void* g) {
    asm volatile("cp.async.cg.shared.global [%0], [%1], 16;" :: "r"(saddr), "l"(g));
}
__device__ __forceinline__ void cpa_commit() {
    asm volatile("cp.async.commit_group;");
}
#define FU(x) __float_as_uint(x)

// ---------------------------------------------------------------------------
// Kernel 1: k = x @ W_K^T (tf32 mma) fused with RoPE.  (unchanged, ~27us)
// ---------------------------------------------------------------------------
#define SX 36
__global__ __launch_bounds__(256) void proj_rope_kernel(
    const float* __restrict__ x, const float* __restrict__ W)
{
    __shared__ float Xs[128 * SX];
    __shared__ float Ws[128 * SX];

    const int tid  = threadIdx.x;
    const int w    = tid >> 5;
    const int lane = tid & 31;
    const int g    = lane >> 2;
    const int tq   = lane & 3;
    const int m0   = blockIdx.x * 128;

    float o[16][4];
    #pragma unroll
    for (int nt = 0; nt < 16; nt++)
        #pragma unroll
        for (int r = 0; r < 4; r++) o[nt][r] = 0.f;

    for (int k0 = 0; k0 < NM; k0 += 32) {
        #pragma unroll
        for (int pass = 0; pass < 4; pass++) {
            int linear = pass * 1024 + tid * 4;
            int row = linear >> 5;
            int c   = linear & 31;
            float4 v = *(const float4*)&x[(size_t)(m0 + row) * NM + k0 + c];
            Xs[row * SX + c + 0] = f2tf(v.x);
            Xs[row * SX + c + 1] = f2tf(v.y);
            Xs[row * SX + c + 2] = f2tf(v.z);
            Xs[row * SX + c + 3] = f2tf(v.w);
            float4 u = *(const float4*)&W[(size_t)row * NM + k0 + c];
            Ws[row * SX + c + 0] = f2tf(u.x);
            Ws[row * SX + c + 1] = f2tf(u.y);
            Ws[row * SX + c + 2] = f2tf(u.z);
            Ws[row * SX + c + 3] = f2tf(u.w);
        }
        __syncthreads();

        #pragma unroll
        for (int kk = 0; kk < 4; kk++) {
            uint32_t a0 = FU(Xs[(w * 16 + g    ) * SX + kk * 8 + tq    ]);
            uint32_t a1 = FU(Xs[(w * 16 + g + 8) * SX + kk * 8 + tq    ]);
            uint32_t a2 = FU(Xs[(w * 16 + g    ) * SX + kk * 8 + tq + 4]);
            uint32_t a3 = FU(Xs[(w * 16 + g + 8) * SX + kk * 8 + tq + 4]);
            #pragma unroll
            for (int nt = 0; nt < 16; nt++) {
                uint32_t b0 = FU(Ws[(nt * 8 + g) * SX + kk * 8 + tq    ]);
                uint32_t b1 = FU(Ws[(nt * 8 + g) * SX + kk * 8 + tq + 4]);
                mma_tf32(o[nt], a0, a1, a2, a3, b0, b1);
            }
        }
        __syncthreads();
    }

    const float THSC = -0.20762050f; // -log2(10000)/64
    const int r0 = m0 + w * 16 + g;
    const int r1 = r0 + 8;
    #pragma unroll
    for (int nt = 0; nt < 16; nt++) {
        int p = nt * 4 + tq;
        float theta = fast_exp2((float)p * THSC);
        float sth, cth;
        __sincosf(theta, &sth, &cth);
        {
            float t1 = o[nt][0], t2 = o[nt][1];
            float2 raw; raw.x = f2tf(t1); raw.y = f2tf(t2);
            *(float2*)&g_k[(size_t)r0 * HS + nt * 8 + 2 * tq] = raw;
            float ev = t1 * cth + t2 * sth;
            float od = -ev * sth + t2 * cth;
            float2 rot; rot.x = f2tf(ev); rot.y = f2tf(od);
            *(float2*)&g_kr[(size_t)r0 * HS + nt * 8 + 2 * tq] = rot;
        }
        {
            float t1 = o[nt][2], t2 = o[nt][3];
            float2 raw; raw.x = f2tf(t1); raw.y = f2tf(t2);
            *(float2*)&g_k[(size_t)r1 * HS + nt * 8 + 2 * tq] = raw;
            float ev = t1 * cth + t2 * sth;
            float od = -ev * sth + t2 * cth;
            float2 rot; rot.x = f2tf(ev); rot.y = f2tf(od);
            *(float2*)&g_kr[(size_t)r1 * HS + nt * 8 + 2 * tq] = rot;
        }
    }
}

// ---------------------------------------------------------------------------
// Kernel 2: causal flash attention, tf32 mma, cp.async double-buffered K/V.
// BM=128 (8 warps), BN=64.  1 CTA/SM.  Q frags in regs; Q stages via buf1.
// Layout (floats): K0@0[64*132], V0@8448[64*136], K1@17152, V1@25600,
//                  P@34304[128*76].  Total 44032 floats = 176128 B.
// ---------------------------------------------------------------------------
#define SQ 132
#define SV 136
#define SP 76
#define KOFF0 0
#define VOFF0 8448
#define KOFF1 17152
#define VOFF1 25600
#define POFF  34304
#define SMEM_ATTN_BYTES (44032 * 4)

__global__ __launch_bounds__(256, 1) void attn_kernel(float* __restrict__ out)
{
    extern __shared__ float sm[];
    float* Ps = sm + POFF;

    const int tid  = threadIdx.x;
    const int w    = tid >> 5;       // 0..7
    const int lane = tid & 31;
    const int g    = lane >> 2;
    const int tq   = lane & 3;
    const int qt   = (NQT128 - 1) - blockIdx.x;   // heavy tiles first
    const int b    = blockIdx.y;

    const float* krot = g_kr + (size_t)b * TT * HS;
    const float* kraw = g_k  + (size_t)b * TT * HS;
    const float C = 1.4426950408889634f * 0.08838834764831845f;

    uint32_t smem_u32;
    {
        asm("{ .reg .u64 t; cvta.to.shared.u64 t, %1; cvt.u32.u64 %0, t; }"
            : "=r"(smem_u32) : "l"(sm));
    }
    const int koff[2] = {KOFF0, KOFF1};
    const int voff[2] = {VOFF0, VOFF1};

    // ---- prefetch tile 0 into buf0 (before Q staging touches buf1) ----
    {
        const float* ks = krot;        // jt = 0
        const float* vs = kraw;
        #pragma unroll
        for (int pass = 0; pass < 8; pass++) {
            int id  = pass * 256 + tid;          // 2048 chunks of 16B
            int row = id >> 5;
            int c4  = id & 31;
            cpa16(smem_u32 + (KOFF0 + row * SQ + 4 * c4) * 4, ks + row * HS + 4 * c4);
            cpa16(smem_u32 + (VOFF0 + row * SV + 4 * c4) * 4, vs + row * HS + 4 * c4);
        }
        cpa_commit();
    }

    // ---- stage Q (128x128) into buf1 region (stride SQ), extract frags ----
    {
        float* Qs = sm + KOFF1;
        const float* qsrc = krot + (size_t)qt * 128 * HS;
        #pragma unroll
        for (int pass = 0; pass < 16; pass++) {
            int linear = pass * 1024 + tid * 4;   // 16384 floats
            int row = linear >> 7;
            int c   = linear & 127;
            *(float4*)&Qs[row * SQ + c] = *(const float4*)&qsrc[linear];
        }
    }
    __syncthreads();

    uint32_t qa[16][4];
    {
        float* Qs = sm + KOFF1;
        #pragma unroll
        for (int kk = 0; kk < 16; kk++) {
            qa[kk][0] = FU(Qs[(w * 16 + g    ) * SQ + kk * 8 + tq    ]);
            qa[kk][1] = FU(Qs[(w * 16 + g + 8) * SQ + kk * 8 + tq    ]);
            qa[kk][2] = FU(Qs[(w * 16 + g    ) * SQ + kk * 8 + tq + 4]);
            qa[kk][3] = FU(Qs[(w * 16 + g + 8) * SQ + kk * 8 + tq + 4]);
        }
    }
    __syncthreads();   // Q region free; iter 0 may now prefetch into buf1

    float o[16][4];
    #pragma unroll
    for (int nt = 0; nt < 16; nt++)
        #pragma unroll
        for (int r = 0; r < 4; r++) o[nt][r] = 0.f;
    float mrow0 = -1e30f, mrow1 = -1e30f, l0 = 0.f, l1 = 0.f;

    const int nTiles = 2 * qt + 2;     // k-tiles of 64 rows

    for (int jt = 0; jt < nTiles; jt++) {
        const int cur = jt & 1;
        // ---- prefetch next tile into the other buffer ----
        if (jt + 1 < nTiles) {
            const int nb = cur ^ 1;
            const float* ks = krot + (size_t)(jt + 1) * 64 * HS;
            const float* vs = kraw + (size_t)(jt + 1) * 64 * HS;
            #pragma unroll
            for (int pass = 0; pass < 8; pass++) {
                int id  = pass * 256 + tid;
                int row = id >> 5;
                int c4  = id & 31;
                cpa16(smem_u32 + (koff[nb] + row * SQ + 4 * c4) * 4, ks + row * HS + 4 * c4);
                cpa16(smem_u32 + (voff[nb] + row * SV + 4 * c4) * 4, vs + row * HS + 4 * c4);
            }
            cpa_commit();
            asm volatile("cp.async.wait_group 1;");
        } else {
            asm volatile("cp.async.wait_group 0;");
        }
        __syncthreads();    // buf[cur] complete and visible to all

        float* Ks = sm + koff[cur];
        float* Vs = sm + voff[cur];

        // ---- S = Q K^T ----
        float sc[8][4];
        #pragma unroll
        for (int nt = 0; nt < 8; nt++)
            #pragma unroll
            for (int r = 0; r < 4; r++) sc[nt][r] = 0.f;

        #pragma unroll
        for (int kk = 0; kk < 16; kk++) {
            #pragma unroll
            for (int nt = 0; nt < 8; nt++) {
                uint32_t b0 = FU(Ks[(nt * 8 + g) * SQ + kk * 8 + tq    ]);
                uint32_t b1 = FU(Ks[(nt * 8 + g) * SQ + kk * 8 + tq + 4]);
                mma_tf32(sc[nt], qa[kk][0], qa[kk][1], qa[kk][2], qa[kk][3], b0, b1);
            }
        }

        // ---- causal mask (only near-diagonal k-tiles need it) ----
        if (jt >= 2 * qt) {
            int r0 = qt * 128 + w * 16 + g;
            int r1 = r0 + 8;
            #pragma unroll
            for (int nt = 0; nt < 8; nt++) {
                int c0 = jt * 64 + nt * 8 + 2 * tq, c1 = c0 + 1;
                if (c0 > r0) sc[nt][0] = -1e30f;
                if (c1 > r0) sc[nt][1] = -1e30f;
                if (c0 > r1) sc[nt][2] = -1e30f;
                if (c1 > r1) sc[nt][3] = -1e30f;
            }
        }

        // ---- online softmax ----
        float tm0 = -1e30f, tm1 = -1e30f;
        #pragma unroll
        for (int nt = 0; nt < 8; nt++) {
            tm0 = fmaxf(tm0, fmaxf(sc[nt][0], sc[nt][1]));
            tm1 = fmaxf(tm1, fmaxf(sc[nt][2], sc[nt][3]));
        }
        tm0 = fmaxf(tm0, __shfl_xor_sync(0xffffffffu, tm0, 1));
        tm0 = fmaxf(tm0, __shfl_xor_sync(0xffffffffu, tm0, 2));
        tm1 = fmaxf(tm1, __shfl_xor_sync(0xffffffffu, tm1, 1));
        tm1 = fmaxf(tm1, __shfl_xor_sync(0xffffffffu, tm1, 2));

        float mn0 = fmaxf(mrow0, tm0);
        float mn1 = fmaxf(mrow1, tm1);
        float fac0 = fast_exp2((mrow0 - mn0) * C);
        float fac1 = fast_exp2((mrow1 - mn1) * C);
        mrow0 = mn0; mrow1 = mn1;

        float ts0 = 0.f, ts1 = 0.f;
        #pragma unroll
        for (int nt = 0; nt < 8; nt++) {
            float p0 = f2tf(fast_exp2((sc[nt][0] - mn0) * C));
            float p1 = f2tf(fast_exp2((sc[nt][1] - mn0) * C));
            float p2 = f2tf(fast_exp2((sc[nt][2] - mn1) * C));
            float p3 = f2tf(fast_exp2((sc[nt][3] - mn1) * C));
            ts0 += p0 + p1; ts1 += p2 + p3;
            sc[nt][0] = p0; sc[nt][1] = p1; sc[nt][2] = p2; sc[nt][3] = p3;
        }
        ts0 += __shfl_xor_sync(0xffffffffu, ts0, 1);
        ts0 += __shfl_xor_sync(0xffffffffu, ts0, 2);
        ts1 += __shfl_xor_sync(0xffffffffu, ts1, 1);
        ts1 += __shfl_xor_sync(0xffffffffu, ts1, 2);
        l0 = l0 * fac0 + ts0;
        l1 = l1 * fac1 + ts1;

        #pragma unroll
        for (int nt = 0; nt < 16; nt++) {
            o[nt][0] *= fac0; o[nt][1] *= fac0;
            o[nt][2] *= fac1; o[nt][3] *= fac1;
        }

        // ---- P store (warp-private rows) then PV ----
        __syncwarp();
        #pragma unroll
        for (int nt = 0; nt < 8; nt++) {
            float2 lo; lo.x = sc[nt][0]; lo.y = sc[nt][1];
            float2 hi; hi.x = sc[nt][2]; hi.y = sc[nt][3];
            *(float2*)&Ps[(w * 16 + g    ) * SP + nt * 8 + 2 * tq] = lo;
            *(float2*)&Ps[(w * 16 + g + 8) * SP + nt * 8 + 2 * tq] = hi;
        }
        __syncwarp();

        #pragma unroll
        for (int kk = 0; kk < 8; kk++) {
            uint32_t pa0 = FU(Ps[(w * 16 + g    ) * SP + kk * 8 + tq    ]);
            uint32_t pa1 = FU(Ps[(w * 16 + g + 8) * SP + kk * 8 + tq    ]);
            uint32_t pa2 = FU(Ps[(w * 16 + g    ) * SP + kk * 8 + tq + 4]);
            uint32_t pa3 = FU(Ps[(w * 16 + g + 8) * SP + kk * 8 + tq + 4]);
            #pragma unroll
            for (int nt = 0; nt < 16; nt++) {
                uint32_t b0 = FU(Vs[(kk * 8 + tq    ) * SV + nt * 8 + g]);
                uint32_t b1 = FU(Vs[(kk * 8 + tq + 4) * SV + nt * 8 + g]);
                mma_tf32(o[nt], pa0, pa1, pa2, pa3, b0, b1);
            }
        }
        __syncthreads();   // all warps done with buf[cur] before overwrite
    }

    // ---- epilogue ----
    float inv0 = 1.0f / l0;
    float inv1 = 1.0f / l1;
    size_t r0 = (size_t)b * TT + (size_t)qt * 128 + w * 16 + g;
    size_t r1 = r0 + 8;
    #pragma unroll
    for (int nt = 0; nt < 16; nt++) {
        float2 lo; lo.x = o[nt][0] * inv0; lo.y = o[nt][1] * inv0;
        float2 hi; hi.x = o[nt][2] * inv1; hi.y = o[nt][3] * inv1;
        *(float2*)&out[r0 * HS + nt * 8 + 2 * tq] = lo;
        *(float2*)&out[r1 * HS + nt * 8 + 2 * tq] = hi;
    }
}

// ---------------------------------------------------------------------------
extern "C" void kernel_launch(void* const* d_in, const int* in_sizes, int n_in,
                              void* d_out, int out_size)
{
    const float* x = (const float*)d_in[0];
    const float* W = (const float*)d_in[1];
    if (n_in >= 2 && in_sizes[0] < in_sizes[1]) {
        x = (const float*)d_in[1];
        W = (const float*)d_in[0];
    }

    cudaFuncSetAttribute(attn_kernel,
                         cudaFuncAttributeMaxDynamicSharedMemorySize,
                         SMEM_ATTN_BYTES);

    proj_rope_kernel<<<MROWS / 128, 256>>>(x, W);
    attn_kernel<<<dim3(NQT128, BB), 256, SMEM_ATTN_BYTES>>>((float*)d_out);
}

// round 8
// speedup vs baseline: 1.0070x; 1.0070x over previous
#include <cuda_runtime.h>
#include <math.h>
#include <stdint.h>

// Problem constants
#define BB 8
#define TT 4096
#define NM 1024
#define HS 128
#define MROWS (BB * TT)
#define NQT128 (TT / 128)        // 32 query tiles of 128 rows

// Scratch
__device__ float g_k [MROWS * HS];   // raw projection (V), tf32-rounded
__device__ float g_kr[MROWS * HS];   // RoPE'd projection (Q,K), tf32-rounded

// ---------------------------------------------------------------------------
__device__ __forceinline__ float fast_exp2(float x) {
    float y;
    asm("ex2.approx.ftz.f32 %0, %1;" : "=f"(y) : "f"(x));
    return y;
}
__device__ __forceinline__ float f2tf(float x) {
    uint32_t r;
    asm("cvt.rna.tf32.f32 %0, %1;" : "=r"(r) : "f"(x));
    return __uint_as_float(r);
}
__device__ __forceinline__ void mma_tf32(float c[4],
                                         uint32_t a0, uint32_t a1, uint32_t a2, uint32_t a3,
                                         uint32_t b0, uint32_t b1) {
    asm volatile(
        "mma.sync.aligned.m16n8k8.row.col.f32.tf32.tf32.f32 "
        "{%0,%1,%2,%3}, {%4,%5,%6,%7}, {%8,%9}, {%0,%1,%2,%3};\n"
        : "+f"(c[0]), "+f"(c[1]), "+f"(c[2]), "+f"(c[3])
        : "r"(a0), "r"(a1), "r"(a2), "r"(a3), "r"(b0), "r"(b1));
}
__device__ __forceinline__ void cpa16(uint32_t saddr, const void* g) {
    asm volatile("cp.async.cg.shared.global [%0], [%1], 16;" :: "r"(saddr), "l"(g));
}
__device__ __forceinline__ void cpa_commit() {
    asm volatile("cp.async.commit_group;");
}
#define FU(x) __float_as_uint(x)

// ---------------------------------------------------------------------------
// Kernel 1: k = x @ W_K^T (tf32 mma) fused with RoPE.
// ---------------------------------------------------------------------------
#define SX 36
__global__ __launch_bounds__(256) void proj_rope_kernel(
    const float* __restrict__ x, const float* __restrict__ W)
{
    __shared__ float Xs[128 * SX];
    __shared__ float Ws[128 * SX];

    const int tid  = threadIdx.x;
    const int w    = tid >> 5;
    const int lane = tid & 31;
    const int g    = lane >> 2;
    const int tq   = lane & 3;
    const int m0   = blockIdx.x * 128;

    float o[16][4];
    #pragma unroll
    for (int nt = 0; nt < 16; nt++)
        #pragma unroll
        for (int r = 0; r < 4; r++) o[nt][r] = 0.f;

    for (int k0 = 0; k0 < NM; k0 += 32) {
        #pragma unroll
        for (int pass = 0; pass < 4; pass++) {
            int linear = pass * 1024 + tid * 4;
            int row = linear >> 5;
            int c   = linear & 31;
            float4 v = *(const float4*)&x[(size_t)(m0 + row) * NM + k0 + c];
            Xs[row * SX + c + 0] = f2tf(v.x);
            Xs[row * SX + c + 1] = f2tf(v.y);
            Xs[row * SX + c + 2] = f2tf(v.z);
            Xs[row * SX + c + 3] = f2tf(v.w);
            float4 u = *(const float4*)&W[(size_t)row * NM + k0 + c];
            Ws[row * SX + c + 0] = f2tf(u.x);
            Ws[row * SX + c + 1] = f2tf(u.y);
            Ws[row * SX + c + 2] = f2tf(u.z);
            Ws[row * SX + c + 3] = f2tf(u.w);
        }
        __syncthreads();

        #pragma unroll
        for (int kk = 0; kk < 4; kk++) {
            uint32_t a0 = FU(Xs[(w * 16 + g    ) * SX + kk * 8 + tq    ]);
            uint32_t a1 = FU(Xs[(w * 16 + g + 8) * SX + kk * 8 + tq    ]);
            uint32_t a2 = FU(Xs[(w * 16 + g    ) * SX + kk * 8 + tq + 4]);
            uint32_t a3 = FU(Xs[(w * 16 + g + 8) * SX + kk * 8 + tq + 4]);
            #pragma unroll
            for (int nt = 0; nt < 16; nt++) {
                uint32_t b0 = FU(Ws[(nt * 8 + g) * SX + kk * 8 + tq    ]);
                uint32_t b1 = FU(Ws[(nt * 8 + g) * SX + kk * 8 + tq + 4]);
                mma_tf32(o[nt], a0, a1, a2, a3, b0, b1);
            }
        }
        __syncthreads();
    }

    const float THSC = -0.20762050f; // -log2(10000)/64
    const int r0 = m0 + w * 16 + g;
    const int r1 = r0 + 8;
    #pragma unroll
    for (int nt = 0; nt < 16; nt++) {
        int p = nt * 4 + tq;
        float theta = fast_exp2((float)p * THSC);
        float sth, cth;
        __sincosf(theta, &sth, &cth);
        {
            float t1 = o[nt][0], t2 = o[nt][1];
            float2 raw; raw.x = f2tf(t1); raw.y = f2tf(t2);
            *(float2*)&g_k[(size_t)r0 * HS + nt * 8 + 2 * tq] = raw;
            float ev = t1 * cth + t2 * sth;
            float od = -ev * sth + t2 * cth;
            float2 rot; rot.x = f2tf(ev); rot.y = f2tf(od);
            *(float2*)&g_kr[(size_t)r0 * HS + nt * 8 + 2 * tq] = rot;
        }
        {
            float t1 = o[nt][2], t2 = o[nt][3];
            float2 raw; raw.x = f2tf(t1); raw.y = f2tf(t2);
            *(float2*)&g_k[(size_t)r1 * HS + nt * 8 + 2 * tq] = raw;
            float ev = t1 * cth + t2 * sth;
            float od = -ev * sth + t2 * cth;
            float2 rot; rot.x = f2tf(ev); rot.y = f2tf(od);
            *(float2*)&g_kr[(size_t)r1 * HS + nt * 8 + 2 * tq] = rot;
        }
    }
}

// ---------------------------------------------------------------------------
// Kernel 2: causal flash attention, tf32 mma, cp.async double-buffered K/V.
// BM=128 (8 warps), BN=64.  1 CTA/SM.  Q frags in regs; Q stages via buf1.
// Layout (floats): K0@0[64*132], V0@8448[64*136], K1@17152, V1@25600,
//                  P@34304[128*76].  Total 44032 floats = 176128 B.
// ---------------------------------------------------------------------------
#define SQ 132
#define SV 136
#define SP 76
#define KOFF0 0
#define VOFF0 8448
#define KOFF1 17152
#define VOFF1 25600
#define POFF  34304
#define SMEM_ATTN_BYTES (44032 * 4)

__global__ __launch_bounds__(256, 1) void attn_kernel(float* __restrict__ out)
{
    extern __shared__ float sm[];
    float* Ps = sm + POFF;

    const int tid  = threadIdx.x;
    const int w    = tid >> 5;       // 0..7
    const int lane = tid & 31;
    const int g    = lane >> 2;
    const int tq   = lane & 3;
    const int qt   = (NQT128 - 1) - blockIdx.x;   // heavy tiles first
    const int b    = blockIdx.y;

    const float* krot = g_kr + (size_t)b * TT * HS;
    const float* kraw = g_k  + (size_t)b * TT * HS;
    const float C = 1.4426950408889634f * 0.08838834764831845f;

    uint32_t smem_u32;
    {
        asm("{ .reg .u64 t; cvta.to.shared.u64 t, %1; cvt.u32.u64 %0, t; }"
            : "=r"(smem_u32) : "l"(sm));
    }
    const int koff[2] = {KOFF0, KOFF1};
    const int voff[2] = {VOFF0, VOFF1};

    // ---- prefetch tile 0 into buf0 (before Q staging touches buf1) ----
    {
        const float* ks = krot;        // jt = 0
        const float* vs = kraw;
        #pragma unroll
        for (int pass = 0; pass < 8; pass++) {
            int id  = pass * 256 + tid;          // 2048 chunks of 16B
            int row = id >> 5;
            int c4  = id & 31;
            cpa16(smem_u32 + (KOFF0 + row * SQ + 4 * c4) * 4, ks + row * HS + 4 * c4);
            cpa16(smem_u32 + (VOFF0 + row * SV + 4 * c4) * 4, vs + row * HS + 4 * c4);
        }
        cpa_commit();
    }

    // ---- stage Q (128x128) into buf1 region (stride SQ), extract frags ----
    {
        float* Qs = sm + KOFF1;
        const float* qsrc = krot + (size_t)qt * 128 * HS;
        #pragma unroll
        for (int pass = 0; pass < 16; pass++) {
            int linear = pass * 1024 + tid * 4;   // 16384 floats
            int row = linear >> 7;
            int c   = linear & 127;
            *(float4*)&Qs[row * SQ + c] = *(const float4*)&qsrc[linear];
        }
    }
    __syncthreads();

    uint32_t qa[16][4];
    {
        float* Qs = sm + KOFF1;
        #pragma unroll
        for (int kk = 0; kk < 16; kk++) {
            qa[kk][0] = FU(Qs[(w * 16 + g    ) * SQ + kk * 8 + tq    ]);
            qa[kk][1] = FU(Qs[(w * 16 + g + 8) * SQ + kk * 8 + tq    ]);
            qa[kk][2] = FU(Qs[(w * 16 + g    ) * SQ + kk * 8 + tq + 4]);
            qa[kk][3] = FU(Qs[(w * 16 + g + 8) * SQ + kk * 8 + tq + 4]);
        }
    }
    __syncthreads();   // Q region free; iter 0 may now prefetch into buf1

    float o[16][4];
    #pragma unroll
    for (int nt = 0; nt < 16; nt++)
        #pragma unroll
        for (int r = 0; r < 4; r++) o[nt][r] = 0.f;
    float mrow0 = -1e30f, mrow1 = -1e30f, l0 = 0.f, l1 = 0.f;

    const int nTiles = 2 * qt + 2;     // k-tiles of 64 rows

    for (int jt = 0; jt < nTiles; jt++) {
        const int cur = jt & 1;
        // ---- prefetch next tile into the other buffer ----
        if (jt + 1 < nTiles) {
            const int nb = cur ^ 1;
            const float* ks = krot + (size_t)(jt + 1) * 64 * HS;
            const float* vs = kraw + (size_t)(jt + 1) * 64 * HS;
            #pragma unroll
            for (int pass = 0; pass < 8; pass++) {
                int id  = pass * 256 + tid;
                int row = id >> 5;
                int c4  = id & 31;
                cpa16(smem_u32 + (koff[nb] + row * SQ + 4 * c4) * 4, ks + row * HS + 4 * c4);
                cpa16(smem_u32 + (voff[nb] + row * SV + 4 * c4) * 4, vs + row * HS + 4 * c4);
            }
            cpa_commit();
            asm volatile("cp.async.wait_group 1;");
        } else {
            asm volatile("cp.async.wait_group 0;");
        }
        __syncthreads();    // buf[cur] complete and visible to all

        float* Ks = sm + koff[cur];
        float* Vs = sm + voff[cur];

        // ---- S = Q K^T ----
        float sc[8][4];
        #pragma unroll
        for (int nt = 0; nt < 8; nt++)
            #pragma unroll
            for (int r = 0; r < 4; r++) sc[nt][r] = 0.f;

        #pragma unroll
        for (int kk = 0; kk < 16; kk++) {
            #pragma unroll
            for (int nt = 0; nt < 8; nt++) {
                uint32_t b0 = FU(Ks[(nt * 8 + g) * SQ + kk * 8 + tq    ]);
                uint32_t b1 = FU(Ks[(nt * 8 + g) * SQ + kk * 8 + tq + 4]);
                mma_tf32(sc[nt], qa[kk][0], qa[kk][1], qa[kk][2], qa[kk][3], b0, b1);
            }
        }

        // ---- causal mask (only near-diagonal k-tiles need it) ----
        if (jt >= 2 * qt) {
            int r0 = qt * 128 + w * 16 + g;
            int r1 = r0 + 8;
            #pragma unroll
            for (int nt = 0; nt < 8; nt++) {
                int c0 = jt * 64 + nt * 8 + 2 * tq, c1 = c0 + 1;
                if (c0 > r0) sc[nt][0] = -1e30f;
                if (c1 > r0) sc[nt][1] = -1e30f;
                if (c0 > r1) sc[nt][2] = -1e30f;
                if (c1 > r1) sc[nt][3] = -1e30f;
            }
        }

        // ---- online softmax ----
        float tm0 = -1e30f, tm1 = -1e30f;
        #pragma unroll
        for (int nt = 0; nt < 8; nt++) {
            tm0 = fmaxf(tm0, fmaxf(sc[nt][0], sc[nt][1]));
            tm1 = fmaxf(tm1, fmaxf(sc[nt][2], sc[nt][3]));
        }
        tm0 = fmaxf(tm0, __shfl_xor_sync(0xffffffffu, tm0, 1));
        tm0 = fmaxf(tm0, __shfl_xor_sync(0xffffffffu, tm0, 2));
        tm1 = fmaxf(tm1, __shfl_xor_sync(0xffffffffu, tm1, 1));
        tm1 = fmaxf(tm1, __shfl_xor_sync(0xffffffffu, tm1, 2));

        float mn0 = fmaxf(mrow0, tm0);
        float mn1 = fmaxf(mrow1, tm1);
        float fac0 = fast_exp2((mrow0 - mn0) * C);
        float fac1 = fast_exp2((mrow1 - mn1) * C);
        mrow0 = mn0; mrow1 = mn1;

        float ts0 = 0.f, ts1 = 0.f;
        #pragma unroll
        for (int nt = 0; nt < 8; nt++) {
            float p0 = f2tf(fast_exp2((sc[nt][0] - mn0) * C));
            float p1 = f2tf(fast_exp2((sc[nt][1] - mn0) * C));
            float p2 = f2tf(fast_exp2((sc[nt][2] - mn1) * C));
            float p3 = f2tf(fast_exp2((sc[nt][3] - mn1) * C));
            ts0 += p0 + p1; ts1 += p2 + p3;
            sc[nt][0] = p0; sc[nt][1] = p1; sc[nt][2] = p2; sc[nt][3] = p3;
        }
        ts0 += __shfl_xor_sync(0xffffffffu, ts0, 1);
        ts0 += __shfl_xor_sync(0xffffffffu, ts0, 2);
        ts1 += __shfl_xor_sync(0xffffffffu, ts1, 1);
        ts1 += __shfl_xor_sync(0xffffffffu, ts1, 2);
        l0 = l0 * fac0 + ts0;
        l1 = l1 * fac1 + ts1;

        #pragma unroll
        for (int nt = 0; nt < 16; nt++) {
            o[nt][0] *= fac0; o[nt][1] *= fac0;
            o[nt][2] *= fac1; o[nt][3] *= fac1;
        }

        // ---- P store (warp-private rows) then PV ----
        __syncwarp();
        #pragma unroll
        for (int nt = 0; nt < 8; nt++) {
            float2 lo; lo.x = sc[nt][0]; lo.y = sc[nt][1];
            float2 hi; hi.x = sc[nt][2]; hi.y = sc[nt][3];
            *(float2*)&Ps[(w * 16 + g    ) * SP + nt * 8 + 2 * tq] = lo;
            *(float2*)&Ps[(w * 16 + g + 8) * SP + nt * 8 + 2 * tq] = hi;
        }
        __syncwarp();

        #pragma unroll
        for (int kk = 0; kk < 8; kk++) {
            uint32_t pa0 = FU(Ps[(w * 16 + g    ) * SP + kk * 8 + tq    ]);
            uint32_t pa1 = FU(Ps[(w * 16 + g + 8) * SP + kk * 8 + tq    ]);
            uint32_t pa2 = FU(Ps[(w * 16 + g    ) * SP + kk * 8 + tq + 4]);
            uint32_t pa3 = FU(Ps[(w * 16 + g + 8) * SP + kk * 8 + tq + 4]);
            #pragma unroll
            for (int nt = 0; nt < 16; nt++) {
                uint32_t b0 = FU(Vs[(kk * 8 + tq    ) * SV + nt * 8 + g]);
                uint32_t b1 = FU(Vs[(kk * 8 + tq + 4) * SV + nt * 8 + g]);
                mma_tf32(o[nt], pa0, pa1, pa2, pa3, b0, b1);
            }
        }
        __syncthreads();   // all warps done with buf[cur] before overwrite
    }

    // ---- epilogue ----
    float inv0 = 1.0f / l0;
    float inv1 = 1.0f / l1;
    size_t r0 = (size_t)b * TT + (size_t)qt * 128 + w * 16 + g;
    size_t r1 = r0 + 8;
    #pragma unroll
    for (int nt = 0; nt < 16; nt++) {
        float2 lo; lo.x = o[nt][0] * inv0; lo.y = o[nt][1] * inv0;
        float2 hi; hi.x = o[nt][2] * inv1; hi.y = o[nt][3] * inv1;
        *(float2*)&out[r0 * HS + nt * 8 + 2 * tq] = lo;
        *(float2*)&out[r1 * HS + nt * 8 + 2 * tq] = hi;
    }
}

// ---------------------------------------------------------------------------
extern "C" void kernel_launch(void* const* d_in, const int* in_sizes, int n_in,
                              void* d_out, int out_size)
{
    const float* x = (const float*)d_in[0];
    const float* W = (const float*)d_in[1];
    if (n_in >= 2 && in_sizes[0] < in_sizes[1]) {
        x = (const float*)d_in[1];
        W = (const float*)d_in[0];
    }

    cudaFuncSetAttribute(attn_kernel,
                         cudaFuncAttributeMaxDynamicSharedMemorySize,
                         SMEM_ATTN_BYTES);

    proj_rope_kernel<<<MROWS / 128, 256>>>(x, W);
    attn_kernel<<<dim3(NQT128, BB), 256, SMEM_ATTN_BYTES>>>((float*)d_out);
}